// round 6
// baseline (speedup 1.0000x reference)
#include <cuda_runtime.h>

#define EMB   64
#define NSPH  16
#define KMAX  24
#define MAX_EDGES 131072

typedef unsigned long long u64;

__device__ int   g_start[MAX_EDGES];
__device__ int   g_count[MAX_EDGES];
__device__ float g_Wt[EMB * EMB];   // g_Wt[i*64+d] = w[d*64+i]; 16KB, L1-resident

__global__ void prep_kernel(const int* __restrict__ id_reduce,
                            const int* __restrict__ Kidx,
                            const float* __restrict__ w, int nT)
{
    int t = blockIdx.x * blockDim.x + threadIdx.x;
    if (t < EMB * EMB) {
        int d = t >> 6, i = t & 63;
        g_Wt[i * EMB + d] = w[t];
    }
    if (t < nT) {
        int e = id_reduce[t];
        if (t == 0 || id_reduce[t - 1] != e) g_start[e] = t;
        if (t == nT - 1 || id_reduce[t + 1] != e) g_count[e] = Kidx[t] + 1;
    }
}

// ---- packed f32x2 helpers ----
__device__ __forceinline__ u64 pack2(float x) {
    u64 r; asm("mov.b64 %0, {%1, %1};" : "=l"(r) : "f"(x)); return r;
}
__device__ __forceinline__ u64 ffma2(u64 a, u64 b, u64 c) {
    u64 d; asm("fma.rn.f32x2 %0, %1, %2, %3;" : "=l"(d) : "l"(a), "l"(b), "l"(c)); return d;
}
__device__ __forceinline__ u64 fmul2(u64 a, u64 b) {
    u64 d; asm("mul.rn.f32x2 %0, %1, %2;" : "=l"(d) : "l"(a), "l"(b)); return d;
}
__device__ __forceinline__ u64 fadd2(u64 a, u64 b) {
    u64 d; asm("add.rn.f32x2 %0, %1, %2;" : "=l"(d) : "l"(a), "l"(b)); return d;
}
__device__ __forceinline__ float4 ldcs4(const float4* p) {
    return __ldcs(p);
}

// One warp per edge. Lane layout: db = lane&7 (d in [8db,8db+8) as 4 f32x2),
// sb = lane>>3 (s in [4sb,4sb+4)). Wt via LDG (L1-resident); streams via LDCS.
__global__ void __launch_bounds__(128, 4)
main_kernel(const float* __restrict__ rbf,
            const float* __restrict__ sph,
            const float* __restrict__ m,
            float* __restrict__ out, int nEdges)
{
    const int lane = threadIdx.x & 31;
    const int db   = lane & 7;
    const int sb   = lane >> 3;

    const int e = blockIdx.x * 4 + (threadIdx.x >> 5);
    if (e >= nEdges) return;

    // ---- stage 2: B[d][s] = sum_i Wt[i][d] * rbf[i][s] ----
    u64 accB[4][4];   // [dp][s]
    #pragma unroll
    for (int dp = 0; dp < 4; dp++)
        #pragma unroll
        for (int s = 0; s < 4; s++) accB[dp][s] = 0ull;

    const float4* rbf0  = (const float4*)(rbf + (size_t)e * (EMB * NSPH) + sb * 4);
    const float4* wbase = (const float4*)(g_Wt + db * 8);

    #pragma unroll 8
    for (int k = 0; k < EMB; k++) {
        float4 wa = __ldg(wbase + k * 16 + 0);
        float4 wb = __ldg(wbase + k * 16 + 1);
        u64 w2[4];
        w2[0] = ((const u64*)&wa)[0];
        w2[1] = ((const u64*)&wa)[1];
        w2[2] = ((const u64*)&wb)[0];
        w2[3] = ((const u64*)&wb)[1];

        float4 r0 = ldcs4(rbf0 + k * 4);
        u64 rd[4] = { pack2(r0.x), pack2(r0.y), pack2(r0.z), pack2(r0.w) };

        #pragma unroll
        for (int dp = 0; dp < 4; dp++)
            #pragma unroll
            for (int s = 0; s < 4; s++)
                accB[dp][s] = ffma2(w2[dp], rd[s], accB[dp][s]);
    }

    // ---- stage 1: A[s][d] = sum_t sph[s][t] * m[start+t][d] (Kidx == arange) ----
    const int start = g_start[e];
    const int count = g_count[e];

    const float* sph_e = sph + (size_t)e * (NSPH * KMAX);
    const float* s0p = sph_e + (4 * sb + 0) * KMAX;
    const float* s1p = sph_e + (4 * sb + 1) * KMAX;
    const float* s2p = sph_e + (4 * sb + 2) * KMAX;
    const float* s3p = sph_e + (4 * sb + 3) * KMAX;

    u64 accA[4][4];   // [s][dp]
    #pragma unroll
    for (int s = 0; s < 4; s++)
        #pragma unroll
        for (int dp = 0; dp < 4; dp++) accA[s][dp] = 0ull;

    const float4* m_base = (const float4*)(m + (size_t)start * EMB + db * 8);

    const int t4 = count & ~3;
    for (int t0 = 0; t0 < t4; t0 += 4) {
        float4 sp0 = __ldcs((const float4*)(s0p + t0));
        float4 sp1 = __ldcs((const float4*)(s1p + t0));
        float4 sp2 = __ldcs((const float4*)(s2p + t0));
        float4 sp3 = __ldcs((const float4*)(s3p + t0));
        #pragma unroll
        for (int j = 0; j < 4; j++) {
            float4 ma = ldcs4(m_base + (t0 + j) * 16 + 0);
            float4 mb = ldcs4(m_base + (t0 + j) * 16 + 1);
            u64 m2[4];
            m2[0] = ((const u64*)&ma)[0];
            m2[1] = ((const u64*)&ma)[1];
            m2[2] = ((const u64*)&mb)[0];
            m2[3] = ((const u64*)&mb)[1];
            u64 sv[4] = { pack2(((const float*)&sp0)[j]),
                          pack2(((const float*)&sp1)[j]),
                          pack2(((const float*)&sp2)[j]),
                          pack2(((const float*)&sp3)[j]) };
            #pragma unroll
            for (int s = 0; s < 4; s++)
                #pragma unroll
                for (int dp = 0; dp < 4; dp++)
                    accA[s][dp] = ffma2(sv[s], m2[dp], accA[s][dp]);
        }
    }
    for (int t = t4; t < count; t++) {
        float4 ma = ldcs4(m_base + t * 16 + 0);
        float4 mb = ldcs4(m_base + t * 16 + 1);
        u64 m2[4];
        m2[0] = ((const u64*)&ma)[0];
        m2[1] = ((const u64*)&ma)[1];
        m2[2] = ((const u64*)&mb)[0];
        m2[3] = ((const u64*)&mb)[1];
        u64 sv[4] = { pack2(__ldcs(s0p + t)), pack2(__ldcs(s1p + t)),
                      pack2(__ldcs(s2p + t)), pack2(__ldcs(s3p + t)) };
        #pragma unroll
        for (int s = 0; s < 4; s++)
            #pragma unroll
            for (int dp = 0; dp < 4; dp++)
                accA[s][dp] = ffma2(sv[s], m2[dp], accA[s][dp]);
    }

    // ---- Hadamard + s-reduction (registers + shfl) ----
    u64 osum[4];
    #pragma unroll
    for (int dp = 0; dp < 4; dp++) {
        u64 acc = fmul2(accB[dp][0], accA[0][dp]);
        acc = ffma2(accB[dp][1], accA[1][dp], acc);
        acc = ffma2(accB[dp][2], accA[2][dp], acc);
        acc = ffma2(accB[dp][3], accA[3][dp], acc);
        osum[dp] = acc;
    }
    #pragma unroll
    for (int off = 8; off <= 16; off <<= 1)
        #pragma unroll
        for (int dp = 0; dp < 4; dp++)
            osum[dp] = fadd2(osum[dp],
                             __shfl_xor_sync(0xffffffffu, osum[dp], off));

    if (sb == 0) {
        float4 o0, o1;
        ((u64*)&o0)[0] = osum[0];
        ((u64*)&o0)[1] = osum[1];
        ((u64*)&o1)[0] = osum[2];
        ((u64*)&o1)[1] = osum[3];
        float4* op = (float4*)(out + (size_t)e * EMB + db * 8);
        op[0] = o0;
        op[1] = o1;
    }
}

extern "C" void kernel_launch(void* const* d_in, const int* in_sizes, int n_in,
                              void* d_out, int out_size)
{
    const float* rbf  = (const float*)d_in[0];
    const float* sph  = (const float*)d_in[1];
    const float* m    = (const float*)d_in[2];
    const float* w    = (const float*)d_in[3];
    const int*   idr  = (const int*)d_in[4];
    const int*   kidx = (const int*)d_in[5];

    const int nEdges = in_sizes[0] / (EMB * NSPH);
    const int nT     = in_sizes[4];

    prep_kernel<<<(nT + 255) / 256, 256>>>(idr, kidx, w, nT);
    main_kernel<<<(nEdges + 3) / 4, 128>>>(rbf, sph, m, (float*)d_out, nEdges);
}

// round 7
// speedup vs baseline: 1.6336x; 1.6336x over previous
#include <cuda_runtime.h>

#define EMB   64
#define NSPH  16
#define KMAX  24
#define MAX_EDGES 131072

__device__ int    g_start[MAX_EDGES];
__device__ int    g_count[MAX_EDGES];
// W in mma-fragment order: g_Wf[(kt*8+nt)*32 + lane] = {b0, b1} for the
// m16n8k8 B-frag (k8n8 col-major): b0 = Wt[kt*8+tig][nt*8+gid], b1 = +4 rows.
__device__ float2 g_Wf[64 * 32];

__global__ void prep_kernel(const int* __restrict__ id_reduce,
                            const int* __restrict__ Kidx,
                            const float* __restrict__ w, int nT)
{
    int t = blockIdx.x * blockDim.x + threadIdx.x;
    if (t < 2048) {
        int frag = t >> 5, lane = t & 31;
        int kt = frag >> 3, nt = frag & 7;
        int gid = lane >> 2, tig = lane & 3;
        int d = nt * 8 + gid;
        int i = kt * 8 + tig;
        float b0 = w[d * EMB + i];
        float b1 = w[d * EMB + i + 4];
        unsigned r0, r1;
        asm("cvt.rna.tf32.f32 %0, %1;" : "=r"(r0) : "f"(b0));
        asm("cvt.rna.tf32.f32 %0, %1;" : "=r"(r1) : "f"(b1));
        g_Wf[t] = make_float2(__uint_as_float(r0), __uint_as_float(r1));
    }
    if (t < nT) {
        int e = id_reduce[t];
        if (t == 0 || id_reduce[t - 1] != e) g_start[e] = t;
        if (t == nT - 1 || id_reduce[t + 1] != e) g_count[e] = Kidx[t] + 1;
    }
}

__device__ __forceinline__ unsigned tf32r(float x) {
    unsigned u; asm("cvt.rna.tf32.f32 %0, %1;" : "=r"(u) : "f"(x)); return u;
}

__device__ __forceinline__ void mma_tf32(float c[4], const unsigned a[4],
                                         unsigned b0, unsigned b1)
{
    asm volatile(
        "mma.sync.aligned.m16n8k8.row.col.f32.tf32.tf32.f32 "
        "{%0,%1,%2,%3},{%4,%5,%6,%7},{%8,%9},{%0,%1,%2,%3};"
        : "+f"(c[0]), "+f"(c[1]), "+f"(c[2]), "+f"(c[3])
        : "r"(a[0]), "r"(a[1]), "r"(a[2]), "r"(a[3]), "r"(b0), "r"(b1));
}

// One warp handles 2 edges. Per edge: P[s,d] = sum_i rbf[i,s]*Wt[i,d] (8x8
// mmas, W frags shared across the pair), Q[s,d] = sum_t sph[s,t]*m[t,d]
// (3x8 mmas, m predicated on t<count). Same C-frag layout -> Hadamard in
// registers, xor-shfl s-reduction, float2 stores. No shared memory.
__global__ void __launch_bounds__(128, 3)
main_kernel(const float* __restrict__ rbf,
            const float* __restrict__ sph,
            const float* __restrict__ m,
            float* __restrict__ out, int nEdges)
{
    const int lane = threadIdx.x & 31;
    const int gid  = lane >> 2;   // 0..7
    const int tig  = lane & 3;    // 0..3

    const int warp = blockIdx.x * 4 + (threadIdx.x >> 5);
    const int e0 = warp * 2;
    if (e0 >= nEdges) return;
    const bool has_e1 = (e0 + 1 < nEdges);
    const int e1 = has_e1 ? e0 + 1 : e0;

    // ---- resident A-fragments: rbf (stage 2) ----
    // A[s][i] = rbf[e][i][s]; frag: a0=(gid,tig+8kt) a1=(gid+8,·) a2=(gid,·+4) a3=(gid+8,·+4)
    unsigned ra0[8][4], ra1[8][4];
    {
        const float* r0 = rbf + (size_t)e0 * (EMB * NSPH);
        const float* r1 = rbf + (size_t)e1 * (EMB * NSPH);
        #pragma unroll
        for (int kt = 0; kt < 8; kt++) {
            int i = kt * 8 + tig;
            ra0[kt][0] = tf32r(r0[i * NSPH + gid]);
            ra0[kt][1] = tf32r(r0[i * NSPH + gid + 8]);
            ra0[kt][2] = tf32r(r0[(i + 4) * NSPH + gid]);
            ra0[kt][3] = tf32r(r0[(i + 4) * NSPH + gid + 8]);
            ra1[kt][0] = tf32r(r1[i * NSPH + gid]);
            ra1[kt][1] = tf32r(r1[i * NSPH + gid + 8]);
            ra1[kt][2] = tf32r(r1[(i + 4) * NSPH + gid]);
            ra1[kt][3] = tf32r(r1[(i + 4) * NSPH + gid + 8]);
        }
    }

    // ---- resident A-fragments: sph (stage 1) ----
    // A[s][t] = sph[e][s][t], row stride KMAX
    unsigned sa0[3][4], sa1[3][4];
    {
        const float* s0 = sph + (size_t)e0 * (NSPH * KMAX);
        const float* s1 = sph + (size_t)e1 * (NSPH * KMAX);
        #pragma unroll
        for (int kt = 0; kt < 3; kt++) {
            int t = kt * 8 + tig;
            sa0[kt][0] = tf32r(s0[gid * KMAX + t]);
            sa0[kt][1] = tf32r(s0[(gid + 8) * KMAX + t]);
            sa0[kt][2] = tf32r(s0[gid * KMAX + t + 4]);
            sa0[kt][3] = tf32r(s0[(gid + 8) * KMAX + t + 4]);
            sa1[kt][0] = tf32r(s1[gid * KMAX + t]);
            sa1[kt][1] = tf32r(s1[(gid + 8) * KMAX + t]);
            sa1[kt][2] = tf32r(s1[gid * KMAX + t + 4]);
            sa1[kt][3] = tf32r(s1[(gid + 8) * KMAX + t + 4]);
        }
    }

    const int st0 = g_start[e0], ct0 = g_count[e0];
    const int st1 = g_start[e1], ct1 = g_count[e1];

    #pragma unroll
    for (int nt = 0; nt < 8; nt++) {
        // ---- P tiles (stage 2) ----
        float p0[4] = {0.f, 0.f, 0.f, 0.f};
        float p1[4] = {0.f, 0.f, 0.f, 0.f};
        #pragma unroll
        for (int kt = 0; kt < 8; kt++) {
            float2 wf = __ldg(&g_Wf[(kt * 8 + nt) * 32 + lane]);
            unsigned wb0 = __float_as_uint(wf.x);
            unsigned wb1 = __float_as_uint(wf.y);
            mma_tf32(p0, ra0[kt], wb0, wb1);
            mma_tf32(p1, ra1[kt], wb0, wb1);
        }

        // ---- Q tiles (stage 1), m predicated on t < count ----
        float q0[4] = {0.f, 0.f, 0.f, 0.f};
        float q1[4] = {0.f, 0.f, 0.f, 0.f};
        #pragma unroll
        for (int kt = 0; kt < 3; kt++) {
            int t = kt * 8 + tig;
            int dcol = nt * 8 + gid;
            unsigned b0 = (t < ct0)     ? tf32r(m[(size_t)(st0 + t) * EMB + dcol])     : 0u;
            unsigned b1 = (t + 4 < ct0) ? tf32r(m[(size_t)(st0 + t + 4) * EMB + dcol]) : 0u;
            mma_tf32(q0, sa0[kt], b0, b1);
            unsigned c0 = (t < ct1)     ? tf32r(m[(size_t)(st1 + t) * EMB + dcol])     : 0u;
            unsigned c1 = (t + 4 < ct1) ? tf32r(m[(size_t)(st1 + t + 4) * EMB + dcol]) : 0u;
            mma_tf32(q1, sa1[kt], c0, c1);
        }

        // ---- Hadamard + s-reduction ----
        // c0:(s=gid, d=2tig) c1:(gid, 2tig+1) c2:(gid+8, 2tig) c3:(gid+8, 2tig+1)
        float h00 = p0[0] * q0[0] + p0[2] * q0[2];
        float h01 = p0[1] * q0[1] + p0[3] * q0[3];
        float h10 = p1[0] * q1[0] + p1[2] * q1[2];
        float h11 = p1[1] * q1[1] + p1[3] * q1[3];
        #pragma unroll
        for (int off = 4; off <= 16; off <<= 1) {
            h00 += __shfl_xor_sync(0xffffffffu, h00, off);
            h01 += __shfl_xor_sync(0xffffffffu, h01, off);
            h10 += __shfl_xor_sync(0xffffffffu, h10, off);
            h11 += __shfl_xor_sync(0xffffffffu, h11, off);
        }
        if (gid == 0)
            *(float2*)(out + (size_t)e0 * EMB + nt * 8 + 2 * tig) = make_float2(h00, h01);
        if (gid == 1 && has_e1)
            *(float2*)(out + (size_t)e1 * EMB + nt * 8 + 2 * tig) = make_float2(h10, h11);
    }
}

extern "C" void kernel_launch(void* const* d_in, const int* in_sizes, int n_in,
                              void* d_out, int out_size)
{
    const float* rbf  = (const float*)d_in[0];
    const float* sph  = (const float*)d_in[1];
    const float* m    = (const float*)d_in[2];
    const float* w    = (const float*)d_in[3];
    const int*   idr  = (const int*)d_in[4];
    const int*   kidx = (const int*)d_in[5];

    const int nEdges = in_sizes[0] / (EMB * NSPH);
    const int nT     = in_sizes[4];

    int prep_elems = nT > 2048 ? nT : 2048;
    prep_kernel<<<(prep_elems + 255) / 256, 256>>>(idr, kidx, w, nT);

    int nwarps = (nEdges + 1) / 2;
    int nblocks = (nwarps + 3) / 4;
    main_kernel<<<nblocks, 128>>>(rbf, sph, m, (float*)d_out, nEdges);
}

// round 8
// speedup vs baseline: 2.3277x; 1.4249x over previous
#include <cuda_runtime.h>

#define EMB   64
#define NSPH  16
#define KMAX  24
#define MAX_EDGES 131072

__device__ int    g_start[MAX_EDGES];
__device__ int    g_count[MAX_EDGES];
// W in mma-fragment order: g_Wf[(kt*8+nt)*32 + lane] = {b0, b1} for the
// m16n8k8 B-frag (k8n8 col-major): b0 = Wt[kt*8+tig][nt*8+gid], b1 = +4 rows.
__device__ float2 g_Wf[64 * 32];

__global__ void prep_kernel(const int* __restrict__ id_reduce,
                            const int* __restrict__ Kidx,
                            const float* __restrict__ w, int nT)
{
    int t = blockIdx.x * blockDim.x + threadIdx.x;
    if (t < 2048) {
        int frag = t >> 5, lane = t & 31;
        int kt = frag >> 3, nt = frag & 7;
        int gid = lane >> 2, tig = lane & 3;
        int d = nt * 8 + gid;
        int i = kt * 8 + tig;
        float b0 = w[d * EMB + i];
        float b1 = w[d * EMB + i + 4];
        unsigned r0, r1;
        asm("cvt.rna.tf32.f32 %0, %1;" : "=r"(r0) : "f"(b0));
        asm("cvt.rna.tf32.f32 %0, %1;" : "=r"(r1) : "f"(b1));
        g_Wf[t] = make_float2(__uint_as_float(r0), __uint_as_float(r1));
    }
    if (t < nT) {
        int e = id_reduce[t];
        if (t == 0 || id_reduce[t - 1] != e) g_start[e] = t;
        if (t == nT - 1 || id_reduce[t + 1] != e) g_count[e] = Kidx[t] + 1;
    }
}

__device__ __forceinline__ unsigned tf32r(float x) {
    unsigned u; asm("cvt.rna.tf32.f32 %0, %1;" : "=r"(u) : "f"(x)); return u;
}

__device__ __forceinline__ void mma_tf32(float c[4], const unsigned a[4],
                                         unsigned b0, unsigned b1)
{
    asm volatile(
        "mma.sync.aligned.m16n8k8.row.col.f32.tf32.tf32.f32 "
        "{%0,%1,%2,%3},{%4,%5,%6,%7},{%8,%9},{%0,%1,%2,%3};"
        : "+f"(c[0]), "+f"(c[1]), "+f"(c[2]), "+f"(c[3])
        : "r"(a[0]), "r"(a[1]), "r"(a[2]), "r"(a[3]), "r"(b0), "r"(b1));
}

// One warp per edge. P[s,d] = sum_i rbf[i,s]*Wt[i,d] (8x8 m16n8k8 tf32 mmas),
// Q[s,d] = sum_t sph[s,t]*m[t,d] (3x8 mmas, m predicated on t<count). Same
// C-frag layout -> Hadamard in registers, xor-shfl s-reduction. No shared
// memory; occupancy-first (launch_bounds caps regs at 128 -> 16 warps/SM).
__global__ void __launch_bounds__(256, 2)
main_kernel(const float* __restrict__ rbf,
            const float* __restrict__ sph,
            const float* __restrict__ m,
            float* __restrict__ out, int nEdges)
{
    const int lane = threadIdx.x & 31;
    const int gid  = lane >> 2;   // 0..7
    const int tig  = lane & 3;    // 0..3

    const int e = blockIdx.x * 8 + (threadIdx.x >> 5);
    if (e >= nEdges) return;

    // ---- resident A-fragments: rbf (stage 2) ----
    // A[s][i] = rbf[e][i][s]; frag rows s=gid/gid+8, cols i=8kt+tig/+4
    unsigned ra[8][4];
    {
        const float* r0 = rbf + (size_t)e * (EMB * NSPH);
        #pragma unroll
        for (int kt = 0; kt < 8; kt++) {
            int i = kt * 8 + tig;
            ra[kt][0] = tf32r(__ldg(&r0[i * NSPH + gid]));
            ra[kt][1] = tf32r(__ldg(&r0[i * NSPH + gid + 8]));
            ra[kt][2] = tf32r(__ldg(&r0[(i + 4) * NSPH + gid]));
            ra[kt][3] = tf32r(__ldg(&r0[(i + 4) * NSPH + gid + 8]));
        }
    }

    // ---- resident A-fragments: sph (stage 1), A[s][t] = sph[e][s][t] ----
    unsigned sa[3][4];
    {
        const float* s0 = sph + (size_t)e * (NSPH * KMAX);
        #pragma unroll
        for (int kt = 0; kt < 3; kt++) {
            int t = kt * 8 + tig;
            sa[kt][0] = tf32r(__ldg(&s0[gid * KMAX + t]));
            sa[kt][1] = tf32r(__ldg(&s0[(gid + 8) * KMAX + t]));
            sa[kt][2] = tf32r(__ldg(&s0[gid * KMAX + t + 4]));
            sa[kt][3] = tf32r(__ldg(&s0[(gid + 8) * KMAX + t + 4]));
        }
    }

    const int st0 = g_start[e];
    const int ct0 = g_count[e];

    #pragma unroll
    for (int nt = 0; nt < 8; nt++) {
        // ---- P tile (stage 2) ----
        float p0[4] = {0.f, 0.f, 0.f, 0.f};
        #pragma unroll
        for (int kt = 0; kt < 8; kt++) {
            float2 wf = __ldg(&g_Wf[(kt * 8 + nt) * 32 + lane]);
            mma_tf32(p0, ra[kt], __float_as_uint(wf.x), __float_as_uint(wf.y));
        }

        // ---- Q tile (stage 1), m predicated on t < count ----
        float q0[4] = {0.f, 0.f, 0.f, 0.f};
        const int dcol = nt * 8 + gid;
        #pragma unroll
        for (int kt = 0; kt < 3; kt++) {
            int t = kt * 8 + tig;
            unsigned b0 = (t < ct0)     ? tf32r(__ldg(&m[(size_t)(st0 + t) * EMB + dcol]))     : 0u;
            unsigned b1 = (t + 4 < ct0) ? tf32r(__ldg(&m[(size_t)(st0 + t + 4) * EMB + dcol])) : 0u;
            mma_tf32(q0, sa[kt], b0, b1);
        }

        // ---- Hadamard + s-reduction ----
        // c0:(s=gid, d=2tig) c1:(gid, 2tig+1) c2:(gid+8, 2tig) c3:(gid+8, 2tig+1)
        float h00 = p0[0] * q0[0] + p0[2] * q0[2];
        float h01 = p0[1] * q0[1] + p0[3] * q0[3];
        #pragma unroll
        for (int off = 4; off <= 16; off <<= 1) {
            h00 += __shfl_xor_sync(0xffffffffu, h00, off);
            h01 += __shfl_xor_sync(0xffffffffu, h01, off);
        }
        if (gid == 0)
            *(float2*)(out + (size_t)e * EMB + nt * 8 + 2 * tig) = make_float2(h00, h01);
    }
}

extern "C" void kernel_launch(void* const* d_in, const int* in_sizes, int n_in,
                              void* d_out, int out_size)
{
    const float* rbf  = (const float*)d_in[0];
    const float* sph  = (const float*)d_in[1];
    const float* m    = (const float*)d_in[2];
    const float* w    = (const float*)d_in[3];
    const int*   idr  = (const int*)d_in[4];
    const int*   kidx = (const int*)d_in[5];

    const int nEdges = in_sizes[0] / (EMB * NSPH);
    const int nT     = in_sizes[4];

    int prep_elems = nT > 2048 ? nT : 2048;
    prep_kernel<<<(prep_elems + 255) / 256, 256>>>(idr, kidx, w, nT);

    main_kernel<<<(nEdges + 7) / 8, 256>>>(rbf, sph, m, (float*)d_out, nEdges);
}

// round 9
// speedup vs baseline: 2.9184x; 1.2538x over previous
#include <cuda_runtime.h>

#define EMB   64
#define NSPH  16
#define KMAX  24
#define MAX_EDGES 131072

__device__ int    g_start[MAX_EDGES];
__device__ int    g_count[MAX_EDGES];
// W in mma-fragment order: g_Wf[(kt*8+nt)*32 + lane] = {b0, b1} for the
// m16n8k8 B-frag (k8n8 col-major): b0 = Wt[kt*8+tig][nt*8+gid], b1 = +4 rows.
__device__ float2 g_Wf[64 * 32];

__global__ void prep_kernel(const int* __restrict__ id_reduce,
                            const int* __restrict__ Kidx,
                            const float* __restrict__ w, int nT)
{
    int t = blockIdx.x * blockDim.x + threadIdx.x;
    if (t < 2048) {
        int frag = t >> 5, lane = t & 31;
        int kt = frag >> 3, nt = frag & 7;
        int gid = lane >> 2, tig = lane & 3;
        int d = nt * 8 + gid;
        int i = kt * 8 + tig;
        float b0 = w[d * EMB + i];
        float b1 = w[d * EMB + i + 4];
        unsigned r0, r1;
        asm("cvt.rna.tf32.f32 %0, %1;" : "=r"(r0) : "f"(b0));
        asm("cvt.rna.tf32.f32 %0, %1;" : "=r"(r1) : "f"(b1));
        g_Wf[t] = make_float2(__uint_as_float(r0), __uint_as_float(r1));
    }
    if (t < nT) {
        int e = id_reduce[t];
        if (t == 0 || id_reduce[t - 1] != e) g_start[e] = t;
        if (t == nT - 1 || id_reduce[t + 1] != e) g_count[e] = Kidx[t] + 1;
    }
}

__device__ __forceinline__ unsigned tf32r(float x) {
    unsigned u; asm("cvt.rna.tf32.f32 %0, %1;" : "=r"(u) : "f"(x)); return u;
}

__device__ __forceinline__ void mma_tf32(float c[4], const unsigned a[4],
                                         unsigned b0, unsigned b1)
{
    asm volatile(
        "mma.sync.aligned.m16n8k8.row.col.f32.tf32.tf32.f32 "
        "{%0,%1,%2,%3},{%4,%5,%6,%7},{%8,%9},{%0,%1,%2,%3};"
        : "+f"(c[0]), "+f"(c[1]), "+f"(c[2]), "+f"(c[3])
        : "r"(a[0]), "r"(a[1]), "r"(a[2]), "r"(a[3]), "r"(b0), "r"(b1));
}

// One warp per edge, phase-batched for MLP:
//   phase Q: batch-load sph frags (12) + ALL m B-frags (48, predicated) ->
//            compute Q[s,d] for all 8 nt tiles (24 mmas) into 32 regs.
//   phase P: batch-load rbf frags (32) -> per nt: 8 W L1-hit loads + 8 mmas,
//            Hadamard vs q[nt], xor-shfl s-reduction, float2 store.
// No shared memory. launch_bounds caps regs at 128 -> 16 warps/SM.
__global__ void __launch_bounds__(256, 2)
main_kernel(const float* __restrict__ rbf,
            const float* __restrict__ sph,
            const float* __restrict__ m,
            float* __restrict__ out, int nEdges)
{
    const int lane = threadIdx.x & 31;
    const int gid  = lane >> 2;   // 0..7
    const int tig  = lane & 3;    // 0..3

    const int e = blockIdx.x * 8 + (threadIdx.x >> 5);
    if (e >= nEdges) return;

    const int st0 = g_start[e];
    const int ct0 = g_count[e];

    // ---- batch 1: sph A-frags + all m B-frags (48 independent DRAM loads) ----
    unsigned sa[3][4];
    {
        const float* s0 = sph + (size_t)e * (NSPH * KMAX);
        #pragma unroll
        for (int kt = 0; kt < 3; kt++) {
            int t = kt * 8 + tig;
            sa[kt][0] = tf32r(__ldg(&s0[gid * KMAX + t]));
            sa[kt][1] = tf32r(__ldg(&s0[(gid + 8) * KMAX + t]));
            sa[kt][2] = tf32r(__ldg(&s0[gid * KMAX + t + 4]));
            sa[kt][3] = tf32r(__ldg(&s0[(gid + 8) * KMAX + t + 4]));
        }
    }

    unsigned mf[8][6];   // [nt][kt*2 + half]
    {
        const float* mb = m + (size_t)st0 * EMB + gid;
        #pragma unroll
        for (int nt = 0; nt < 8; nt++) {
            #pragma unroll
            for (int kt = 0; kt < 3; kt++) {
                int t = kt * 8 + tig;
                mf[nt][kt * 2 + 0] = (t < ct0)
                    ? tf32r(__ldg(mb + (size_t)t * EMB + nt * 8)) : 0u;
                mf[nt][kt * 2 + 1] = (t + 4 < ct0)
                    ? tf32r(__ldg(mb + (size_t)(t + 4) * EMB + nt * 8)) : 0u;
            }
        }
    }

    // ---- Q phase: all 8 tiles ----
    float q[8][4];
    #pragma unroll
    for (int nt = 0; nt < 8; nt++) {
        q[nt][0] = q[nt][1] = q[nt][2] = q[nt][3] = 0.f;
        #pragma unroll
        for (int kt = 0; kt < 3; kt++)
            mma_tf32(q[nt], sa[kt], mf[nt][kt * 2], mf[nt][kt * 2 + 1]);
    }

    // ---- batch 2: rbf A-frags (32 independent DRAM loads) ----
    unsigned ra[8][4];
    {
        const float* r0 = rbf + (size_t)e * (EMB * NSPH);
        #pragma unroll
        for (int kt = 0; kt < 8; kt++) {
            int i = kt * 8 + tig;
            ra[kt][0] = tf32r(__ldg(&r0[i * NSPH + gid]));
            ra[kt][1] = tf32r(__ldg(&r0[i * NSPH + gid + 8]));
            ra[kt][2] = tf32r(__ldg(&r0[(i + 4) * NSPH + gid]));
            ra[kt][3] = tf32r(__ldg(&r0[(i + 4) * NSPH + gid + 8]));
        }
    }

    // ---- P phase + Hadamard + s-reduction + store ----
    #pragma unroll
    for (int nt = 0; nt < 8; nt++) {
        float p0[4] = {0.f, 0.f, 0.f, 0.f};
        #pragma unroll
        for (int kt = 0; kt < 8; kt++) {
            float2 wf = __ldg(&g_Wf[(kt * 8 + nt) * 32 + lane]);
            mma_tf32(p0, ra[kt], __float_as_uint(wf.x), __float_as_uint(wf.y));
        }

        // c0:(s=gid, d=2tig) c1:(gid, 2tig+1) c2:(gid+8, 2tig) c3:(gid+8, 2tig+1)
        float h00 = p0[0] * q[nt][0] + p0[2] * q[nt][2];
        float h01 = p0[1] * q[nt][1] + p0[3] * q[nt][3];
        #pragma unroll
        for (int off = 4; off <= 16; off <<= 1) {
            h00 += __shfl_xor_sync(0xffffffffu, h00, off);
            h01 += __shfl_xor_sync(0xffffffffu, h01, off);
        }
        if (gid == 0)
            *(float2*)(out + (size_t)e * EMB + nt * 8 + 2 * tig) = make_float2(h00, h01);
    }
}

extern "C" void kernel_launch(void* const* d_in, const int* in_sizes, int n_in,
                              void* d_out, int out_size)
{
    const float* rbf  = (const float*)d_in[0];
    const float* sph  = (const float*)d_in[1];
    const float* m    = (const float*)d_in[2];
    const float* w    = (const float*)d_in[3];
    const int*   idr  = (const int*)d_in[4];
    const int*   kidx = (const int*)d_in[5];

    const int nEdges = in_sizes[0] / (EMB * NSPH);
    const int nT     = in_sizes[4];

    int prep_elems = nT > 2048 ? nT : 2048;
    prep_kernel<<<(prep_elems + 255) / 256, 256>>>(idr, kidx, w, nT);

    main_kernel<<<(nEdges + 7) / 8, 256>>>(rbf, sph, m, (float*)d_out, nEdges);
}